// round 14
// baseline (speedup 1.0000x reference)
#include <cuda_runtime.h>
#include <cuda_bf16.h>
#include <cuda_fp16.h>
#include <cstdint>

#define BATCH   256
#define HDIM    512
#define EMBD    256
#define CFEAT   512
#define HWSZ    64
#define NSTEP   257
#define KDIM    1029
#define KP2     1088
#define NCOL    2304
#define NROWS   (BATCH*NSTEP)

// ---------------- device scratch ----------------
__device__ float g_c[BATCH*HDIM];
__device__ __half g_xem[BATCH*HWSZ*EMBD];
__device__ __half g_bbh[BATCH*CFEAT*HWSZ];
__device__ float g_y[NROWS*128];
__device__ float g_gem[BATCH*EMBD];
__device__ __half g_Ah[BATCH*KP2];
__device__ __half g_Bh[(size_t)NCOL*KP2];
__device__ float g_bsum[2048];
__device__ __nv_bfloat16 g_Phi[BATCH*100*512];
__device__ __nv_bfloat16 g_Plo[BATCH*100*512];
__device__ __nv_bfloat16 g_Chi[9*256*512];
__device__ __nv_bfloat16 g_Clo[9*256*512];
__device__ __nv_bfloat16 g_Hhi[(size_t)NSTEP*BATCH*HDIM];
__device__ __nv_bfloat16 g_Hlo[(size_t)NSTEP*BATCH*HDIM];
__device__ __nv_bfloat16 g_Wfhi[128*512];
__device__ __nv_bfloat16 g_Wflo[128*512];

// ---------------- math helpers ----------------
__device__ __forceinline__ float ftanh(float x){            // accurate (LSTM gates)
    float x2 = x*x;
    float p = x*(135135.f + x2*(17325.f + x2*(378.f + x2)));
    float q = 135135.f + x2*(62370.f + x2*(3150.f + x2*28.f));
    float r = __int_as_float(0x7EF311C3u - __float_as_int(q));
    r = r*(2.f - q*r);
    r = r*(2.f - q*r);
    r = r*(2.f - q*r);
    float t = p*r;
    return fmaxf(-1.f, fminf(1.f, t));
}
__device__ __forceinline__ float fsig(float x){
    return 0.5f + 0.5f*ftanh(0.5f*x);
}
__device__ __forceinline__ float fptanh(float x){           // cheap (attn scores)
    x = fmaxf(-4.8f, fminf(4.8f, x));
    float x2 = x*x;
    float p = x*(945.f + x2*(105.f + x2));
    float q = 945.f + x2*(420.f + x2*15.f);
    float r = __int_as_float(0x7EF311C3u - __float_as_int(q));
    r = r*(2.f - q*r);
    r = r*(2.f - q*r);
    float t = p*r;
    return fmaxf(-1.f, fminf(1.f, t));
}

// ---------------- PTX helpers ----------------
__device__ __forceinline__ uint32_t smem_u32(const void* p){
    uint32_t a;
    asm("{ .reg .u64 t; cvta.to.shared.u64 t, %1; cvt.u32.u64 %0, t; }" : "=r"(a) : "l"(p));
    return a;
}
#define CP_ASYNC16(dst, src) \
    asm volatile("cp.async.cg.shared.global [%0], [%1], 16;" :: "r"(dst), "l"(src))
#define CP_COMMIT()  asm volatile("cp.async.commit_group;" ::: "memory")
#define CP_WAIT(n)   asm volatile("cp.async.wait_group %0;" :: "n"(n) : "memory")

__device__ __forceinline__ void ldm_x4(uint32_t* r, uint32_t addr){
    asm volatile("ldmatrix.sync.aligned.m8n8.x4.shared.b16 {%0,%1,%2,%3}, [%4];"
        : "=r"(r[0]), "=r"(r[1]), "=r"(r[2]), "=r"(r[3]) : "r"(addr));
}
__device__ __forceinline__ void ldm_x2(uint32_t* r, uint32_t addr){
    asm volatile("ldmatrix.sync.aligned.m8n8.x2.shared.b16 {%0,%1}, [%2];"
        : "=r"(r[0]), "=r"(r[1]) : "r"(addr));
}
__device__ __forceinline__ void mma_bf16(float* c, const uint32_t* a, const uint32_t* b){
    asm volatile("mma.sync.aligned.m16n8k16.row.col.f32.bf16.bf16.f32 "
        "{%0,%1,%2,%3}, {%4,%5,%6,%7}, {%8,%9}, {%0,%1,%2,%3};"
        : "+f"(c[0]), "+f"(c[1]), "+f"(c[2]), "+f"(c[3])
        : "r"(a[0]), "r"(a[1]), "r"(a[2]), "r"(a[3]), "r"(b[0]), "r"(b[1]));
}
__device__ __forceinline__ void mma_f16(float* c, const uint32_t* a, const uint32_t* b){
    asm volatile("mma.sync.aligned.m16n8k16.row.col.f32.f16.f16.f32 "
        "{%0,%1,%2,%3}, {%4,%5,%6,%7}, {%8,%9}, {%0,%1,%2,%3};"
        : "+f"(c[0]), "+f"(c[1]), "+f"(c[2]), "+f"(c[3])
        : "r"(a[0]), "r"(a[1]), "r"(a[2]), "r"(a[3]), "r"(b[0]), "r"(b[1]));
}

// smem geometry
#define MATB     9216
#define BUFB4    36864
#define OFF_BS4  73728
#define SMEM_G4  (OFF_BS4 + 256)
#define BUFB2    18432
#define OFF_BS2  36864
#define SMEM_G2  (OFF_BS2 + 256)

// ---------------- weight prep ----------------
__global__ void k_wct2(const float* __restrict__ Wih, const float* __restrict__ Whh,
                       const float* __restrict__ bih, const float* __restrict__ bhh,
                       const float* __restrict__ Wch){
    int col = blockIdx.x;
    if (col < 2048){
        int j = col >> 2, g = col & 3;
        int row = g*512 + j;
        for (int k = threadIdx.x; k < KP2; k += 256){
            float v = 0.f;
            if (k < 512)        v = Whh[row*512 + k];
            else if (k < 1024)  v = Wih[row*517 + (k - 512)];
            else if (k < 1029)  v = Wih[row*517 + 512 + (k - 1024)];
            g_Bh[(size_t)col*KP2 + k] = __float2half_rn(v);
        }
        if (threadIdx.x == 0) g_bsum[col] = bih[row] + bhh[row];
    } else {
        int e = col - 2048;
        for (int k = threadIdx.x; k < KP2; k += 256){
            float v = (k < 512) ? Wch[e*512 + k] : 0.f;
            g_Bh[(size_t)col*KP2 + k] = __float2half_rn(v);
        }
    }
}
__global__ void k_wc(const float* __restrict__ Kcf){
    int idx = blockIdx.x*256 + threadIdx.x;
    int c = idx & 511, r = idx >> 9;
    int e = r & 255, tap = r >> 8;
    float v = Kcf[e*4608 + c*9 + tap];
    __nv_bfloat16 hi = __float2bfloat16_rn(v);
    g_Chi[idx] = hi;
    g_Clo[idx] = __float2bfloat16_rn(v - __bfloat162float(hi));
}
__global__ void k_im2(const float* __restrict__ bbf){
    int b = blockIdx.x;
    for (int idx = threadIdx.x; idx < 100*512; idx += 256){
        int pos = idx >> 9, c = idx & 511;
        int py = pos/10 - 1, px = pos%10 - 1;
        float v = 0.f;
        if (py >= 0 && py < 8 && px >= 0 && px < 8)
            v = bbf[(b*512 + c)*64 + py*8 + px];
        __nv_bfloat16 hi = __float2bfloat16_rn(v);
        g_Phi[b*51200 + idx] = hi;
        g_Plo[b*51200 + idx] = __float2bfloat16_rn(v - __bfloat162float(hi));
    }
}
__global__ void k_bbh(const float* __restrict__ bbf){
    int idx = blockIdx.x*256 + threadIdx.x;
    const float4 v = ((const float4*)bbf)[idx];
    __half2 h0 = __floats2half2_rn(v.x, v.y);
    __half2 h1 = __floats2half2_rn(v.z, v.w);
    ((uint2*)g_bbh)[idx] = make_uint2(*(uint32_t*)&h0, *(uint32_t*)&h1);
}
__global__ void k_wfc(const float* __restrict__ Wfc){
    int col = blockIdx.x;
    for (int k = threadIdx.x; k < 512; k += 256){
        float v = (col < 123) ? Wfc[col*512 + k] : 0.f;
        __nv_bfloat16 hi = __float2bfloat16_rn(v);
        g_Wfhi[col*512 + k] = hi;
        g_Wflo[col*512 + k] = __float2bfloat16_rn(v - __bfloat162float(hi));
    }
}

// ---------------- init hc ----------------
__global__ void k_init(const float* __restrict__ z, const float* __restrict__ W,
                       const float* __restrict__ bias){
    int b = blockIdx.x, tid = threadIdx.x;
    __shared__ float zs[128];
    if (tid < 128) zs[tid] = z[b*128 + tid];
    if (tid < 59) g_Ah[b*KP2 + KDIM + tid] = __float2half_rn(0.f);
    __syncthreads();
    for (int j = tid; j < 1024; j += 256){
        const float4* wr = (const float4*)(W + j*128);
        const float4* zr = (const float4*)zs;
        float acc = bias[j];
        #pragma unroll 8
        for (int k = 0; k < 32; k++){
            float4 w = wr[k], zz = zr[k];
            acc += w.x*zz.x + w.y*zz.y + w.z*zz.z + w.w*zz.w;
        }
        float v = ftanh(acc);
        if (j < 512) g_Ah[b*KP2 + j] = __float2half_rn(v);
        else         g_c[b*512 + (j - 512)] = v;
    }
}

// ---------------- conv as 9-tap HMMA GEMM (bf16 3-term) ----------------
__device__ __forceinline__ void stage_conv(uint32_t sb, int buf, int cc,
                                           int mb, int nb, int tid){
    int tap = cc >> 3, kc = cc & 7;
    int toff = (tap/3)*10 + (tap%3);
    uint32_t dbase = sb + buf*BUFB4;
    #pragma unroll
    for (int i = 0; i < 2; i++){
        int idx = tid + i*256;
        int r = idx >> 3, q = idx & 7;
        int arow = mb*100 + (r >> 3)*10 + (r & 7) + toff;
        size_t so = (size_t)arow*512 + kc*64 + q*8;
        uint32_t dst = dbase + r*144 + q*16;
        CP_ASYNC16(dst,        g_Phi + so);
        CP_ASYNC16(dst + MATB, g_Plo + so);
        int brow = tap*256 + nb*64 + r;
        size_t bo = (size_t)brow*512 + kc*64 + q*8;
        CP_ASYNC16(dst + 2*MATB, g_Chi + bo);
        CP_ASYNC16(dst + 3*MATB, g_Clo + bo);
    }
}
__global__ void __launch_bounds__(256)
k_cgmm(const float* __restrict__ bcf){
    extern __shared__ char sm[];
    int tid = threadIdx.x;
    int wid = tid >> 5, lane = tid & 31;
    int mb = blockIdx.x, nb = blockIdx.y;
    uint32_t sb = smem_u32(sm);
    float* bs = (float*)(sm + OFF_BS4);
    if (tid < 64) bs[tid] = bcf[nb*64 + tid];

    int wm = wid & 1, wn = wid >> 1;
    float acc[2][2][4];
    #pragma unroll
    for (int mi = 0; mi < 2; mi++)
        #pragma unroll
        for (int ni = 0; ni < 2; ni++)
            #pragma unroll
            for (int q = 0; q < 4; q++) acc[mi][ni][q] = 0.f;

    uint32_t aRow = (uint32_t)(wm*32 + (lane & 15));
    uint32_t aCol = (uint32_t)((lane >> 4) * 8);
    uint32_t bRow = (uint32_t)(wn*16 + (lane & 7));
    uint32_t bCol = (uint32_t)(((lane >> 3) & 1) * 8);

    stage_conv(sb, 0, 0, mb, nb, tid);
    CP_COMMIT();
    for (int cc = 0; cc < 72; cc++){
        int buf = cc & 1;
        if (cc + 1 < 72){
            stage_conv(sb, buf ^ 1, cc + 1, mb, nb, tid);
            CP_COMMIT();
            CP_WAIT(1);
        } else CP_WAIT(0);
        __syncthreads();
        uint32_t base = sb + buf*BUFB4;
        #pragma unroll
        for (int ks = 0; ks < 4; ks++){
            uint32_t kb = (uint32_t)(ks*32);
            uint32_t ah[2][4], al[2][4], bh[2][2], bl[2][2];
            #pragma unroll
            for (int mi = 0; mi < 2; mi++){
                uint32_t ao = (aRow + mi*16)*144 + kb + aCol*2;
                ldm_x4(ah[mi], base + ao);
                ldm_x4(al[mi], base + MATB + ao);
            }
            #pragma unroll
            for (int ni = 0; ni < 2; ni++){
                uint32_t bo = (bRow + ni*8)*144 + kb + bCol*2;
                ldm_x2(bh[ni], base + 2*MATB + bo);
                ldm_x2(bl[ni], base + 3*MATB + bo);
            }
            #pragma unroll
            for (int mi = 0; mi < 2; mi++)
                #pragma unroll
                for (int ni = 0; ni < 2; ni++){
                    mma_bf16(acc[mi][ni], ah[mi], bh[ni]);
                    mma_bf16(acc[mi][ni], ah[mi], bl[ni]);
                    mma_bf16(acc[mi][ni], al[mi], bh[ni]);
                }
        }
        __syncthreads();
    }
    float* Cs = (float*)sm;
    #pragma unroll
    for (int mi = 0; mi < 2; mi++)
        #pragma unroll
        for (int ni = 0; ni < 2; ni++){
            int r0 = wm*32 + mi*16 + (lane >> 2);
            int c0 = wn*16 + ni*8 + (lane & 3)*2;
            Cs[r0*68 + c0]         = acc[mi][ni][0];
            Cs[r0*68 + c0 + 1]     = acc[mi][ni][1];
            Cs[(r0+8)*68 + c0]     = acc[mi][ni][2];
            Cs[(r0+8)*68 + c0 + 1] = acc[mi][ni][3];
        }
    __syncthreads();
    #pragma unroll
    for (int i = 0; i < 4; i++){
        int idx = tid + i*256;
        int r = idx >> 4, jl = idx & 15;
        float4 g4 = *(const float4*)&Cs[r*68 + jl*4];
        float4 b4 = *(const float4*)&bs[jl*4];
        __half2 h0 = __floats2half2_rn(g4.x+b4.x, g4.y+b4.y);
        __half2 h1 = __floats2half2_rn(g4.z+b4.z, g4.w+b4.w);
        uint2 pk = make_uint2(*(uint32_t*)&h0, *(uint32_t*)&h1);
        *(uint2*)&g_xem[(mb*64 + r)*256 + nb*64 + jl*4] = pk;
    }
}

// ---------------- attention (FMA-poly scores) ----------------
__global__ void k_attn2(int t,
                        const float* __restrict__ Watt, const float* __restrict__ batt,
                        const float* __restrict__ sketch){
    int b0 = blockIdx.x * 2, tid = threadIdx.x;
    __shared__ float g_s[2][256];
    __shared__ float sc[2][64];

    #pragma unroll
    for (int i = 0; i < 2; i++){
        int idx = tid + i*256;
        int bb = idx >> 8, e = idx & 255;
        g_s[bb][e] = g_gem[(b0+bb)*EMBD + e];
    }
    __syncthreads();
    {
        int pair = tid >> 1, half = tid & 1;
        int bb = pair >> 6, p = pair & 63;
        const uint2* xr = (const uint2*)(g_xem + ((b0+bb)*HWSZ + p)*EMBD + half*128);
        const float4* wa = (const float4*)(Watt + half*128);
        const float4* gv4 = (const float4*)(g_s[bb] + half*128);
        float acc = 0.f;
        #pragma unroll 4
        for (int k = 0; k < 32; k++){
            uint2 xu = xr[k];
            float2 x0 = __half22float2(*(__half2*)&xu.x);
            float2 x1 = __half22float2(*(__half2*)&xu.y);
            float4 w = wa[k], gv = gv4[k];
            acc += fptanh(x0.x+gv.x)*w.x + fptanh(x0.y+gv.y)*w.y
                 + fptanh(x1.x+gv.z)*w.z + fptanh(x1.y+gv.w)*w.w;
        }
        acc += __shfl_xor_sync(0xffffffffu, acc, 1);
        if (half == 0) sc[bb][p] = acc + batt[0];
    }
    __syncthreads();
    if (tid < 64){
        int bb = tid >> 5, lane = tid & 31;
        float v0 = sc[bb][lane], v1 = sc[bb][lane+32];
        float m = fmaxf(v0, v1);
        #pragma unroll
        for (int o = 16; o; o >>= 1) m = fmaxf(m, __shfl_xor_sync(0xffffffffu, m, o));
        float e0 = __expf(v0 - m), e1 = __expf(v1 - m);
        float s = e0 + e1;
        #pragma unroll
        for (int o = 16; o; o >>= 1) s += __shfl_xor_sync(0xffffffffu, s, o);
        float inv = __fdividef(1.f, s);
        sc[bb][lane] = e0*inv; sc[bb][lane+32] = e1*inv;
    }
    __syncthreads();
    #pragma unroll
    for (int bb = 0; bb < 2; bb++){
        #pragma unroll
        for (int cc = 0; cc < 2; cc++){
            int ch = tid + cc*256;
            const uint2* fr = (const uint2*)(g_bbh + ((b0+bb)*CFEAT + ch)*HWSZ);
            float acc = 0.f;
            #pragma unroll
            for (int k = 0; k < 16; k++){
                uint2 fu = fr[k];
                float2 f0 = __half22float2(*(__half2*)&fu.x);
                float2 f1 = __half22float2(*(__half2*)&fu.y);
                acc += sc[bb][k*4+0]*f0.x + sc[bb][k*4+1]*f0.y
                     + sc[bb][k*4+2]*f1.x + sc[bb][k*4+3]*f1.y;
            }
            g_Ah[(b0+bb)*KP2 + 512 + ch] = __float2half_rn(acc);
        }
    }
    if (tid < 10){
        int bb = tid / 5, d = tid % 5;
        float v = (t == 0) ? ((d == 2) ? 1.f : 0.f)
                           : sketch[((t-1)*BATCH + (b0+bb))*5 + d];
        g_Ah[(b0+bb)*KP2 + 1024 + d] = __float2half_rn(v);
    }
}

// ---------------- gates GEMM staging (2 matrices: A, B) --------------
__device__ __forceinline__ void stage_chunk(uint32_t sb, int buf, int kc,
                                            int mb, int nb, int tid){
    uint32_t dbase = sb + buf*BUFB2;
    #pragma unroll
    for (int i = 0; i < 2; i++){
        int idx = tid + i*256;
        int r = idx >> 3, q = idx & 7;
        size_t so = (size_t)(mb*64 + r)*KP2 + kc*64 + q*8;
        uint32_t dst = dbase + r*144 + q*16;
        CP_ASYNC16(dst, g_Ah + so);
        size_t bo = (size_t)(nb*64 + r)*KP2 + kc*64 + q*8;
        CP_ASYNC16(dst + MATB, g_Bh + bo);
    }
}

// ---------------- gates/gem 1-term fp16 HMMA GEMM ----------------
// mode 1 (gem):  K 0..511 (nkc=8),  nb = by+32 -> g_gem (+bch)
// mode 2 (full): K 0..1087 (nkc=17), nb = by   -> + bsum -> LSTM epilogue
__global__ void __launch_bounds__(256)
k_gmm(int mode, int nkc, int t, const float* __restrict__ bch){
    extern __shared__ char sm[];
    int tid = threadIdx.x;
    int wid = tid >> 5, lane = tid & 31;
    int mb = blockIdx.x;
    int nb = (mode == 1) ? (blockIdx.y + 32) : blockIdx.y;
    uint32_t sb = smem_u32(sm);

    float* bs = (float*)(sm + OFF_BS2);
    if (mode == 2){ if (tid < 64) bs[tid] = g_bsum[nb*64 + tid]; }
    else          { if (tid < 64) bs[tid] = bch[(nb-32)*64 + tid]; }

    int wm = wid & 1, wn = wid >> 1;
    float acc[2][2][4];
    #pragma unroll
    for (int mi = 0; mi < 2; mi++)
        #pragma unroll
        for (int ni = 0; ni < 2; ni++)
            #pragma unroll
            for (int q = 0; q < 4; q++) acc[mi][ni][q] = 0.f;

    uint32_t aRow = (uint32_t)(wm*32 + (lane & 15));
    uint32_t aCol = (uint32_t)((lane >> 4) * 8);
    uint32_t bRow = (uint32_t)(wn*16 + (lane & 7));
    uint32_t bCol = (uint32_t)(((lane >> 3) & 1) * 8);

    stage_chunk(sb, 0, 0, mb, nb, tid);
    CP_COMMIT();
    for (int i = 0; i < nkc; i++){
        int buf = i & 1;
        if (i + 1 < nkc){
            stage_chunk(sb, buf ^ 1, i + 1, mb, nb, tid);
            CP_COMMIT();
            CP_WAIT(1);
        } else CP_WAIT(0);
        __syncthreads();
        uint32_t base = sb + buf*BUFB2;
        #pragma unroll
        for (int ks = 0; ks < 4; ks++){
            uint32_t kb = (uint32_t)(ks*32);
            uint32_t ah[2][4], bh[2][2];
            #pragma unroll
            for (int mi = 0; mi < 2; mi++){
                uint32_t ao = (aRow + mi*16)*144 + kb + aCol*2;
                ldm_x4(ah[mi], base + ao);
            }
            #pragma unroll
            for (int ni = 0; ni < 2; ni++){
                uint32_t bo = (bRow + ni*8)*144 + kb + bCol*2;
                ldm_x2(bh[ni], base + MATB + bo);
            }
            #pragma unroll
            for (int mi = 0; mi < 2; mi++)
                #pragma unroll
                for (int ni = 0; ni < 2; ni++)
                    mma_f16(acc[mi][ni], ah[mi], bh[ni]);
        }
        __syncthreads();
    }

    float* Cs = (float*)sm;
    #pragma unroll
    for (int mi = 0; mi < 2; mi++)
        #pragma unroll
        for (int ni = 0; ni < 2; ni++){
            int r0 = wm*32 + mi*16 + (lane >> 2);
            int c0 = wn*16 + ni*8 + (lane & 3)*2;
            Cs[r0*68 + c0]         = acc[mi][ni][0];
            Cs[r0*68 + c0 + 1]     = acc[mi][ni][1];
            Cs[(r0+8)*68 + c0]     = acc[mi][ni][2];
            Cs[(r0+8)*68 + c0 + 1] = acc[mi][ni][3];
        }
    __syncthreads();

    if (mode == 1){
        #pragma unroll
        for (int i = 0; i < 4; i++){
            int idx = tid + i*256;
            int bl_ = idx >> 4, jl = idx & 15;
            int b = mb*64 + bl_;
            float4 g4 = *(const float4*)&Cs[bl_*68 + jl*4];
            float4 b4 = *(const float4*)&bs[jl*4];
            *(float4*)&g_gem[b*EMBD + (nb-32)*64 + jl*4] =
                make_float4(g4.x+b4.x, g4.y+b4.y, g4.z+b4.z, g4.w+b4.w);
        }
    } else {
        #pragma unroll
        for (int i = 0; i < 4; i++){
            int idx = tid + i*256;
            int bl_ = idx >> 4, jl = idx & 15;
            int b = mb*64 + bl_;
            int j = nb*16 + jl;
            float4 g4 = *(const float4*)&Cs[bl_*68 + jl*4];
            float4 b4 = *(const float4*)&bs[jl*4];
            float iv = fsig (g4.x + b4.x);
            float fv = fsig (g4.y + b4.y);
            float gv = ftanh(g4.z + b4.z);
            float ov = fsig (g4.w + b4.w);
            float cold = g_c[b*512 + j];
            float cnew = fv*cold + iv*gv;
            float hnew = ov*ftanh(cnew);
            g_c[b*512 + j] = cnew;
            g_Ah[b*KP2 + j] = __float2half_rn(hnew);
            __nv_bfloat16 hi = __float2bfloat16_rn(hnew);
            size_t hidx = (size_t)(t*BATCH + b)*512 + j;
            g_Hhi[hidx] = hi;
            g_Hlo[hidx] = __float2bfloat16_rn(hnew - __bfloat162float(hi));
        }
    }
}

// ---------------- projection GEMM (bf16 3-term) ----------------
__device__ __forceinline__ void stage_proj(uint32_t sb, int buf, int kc,
                                           int mb, int nb, int tid){
    uint32_t dbase = sb + buf*BUFB4;
    #pragma unroll
    for (int i = 0; i < 2; i++){
        int idx = tid + i*256;
        int r = idx >> 3, q = idx & 7;
        size_t so = (size_t)(mb*64 + r)*512 + kc*64 + q*8;
        uint32_t dst = dbase + r*144 + q*16;
        CP_ASYNC16(dst,        g_Hhi + so);
        CP_ASYNC16(dst + MATB, g_Hlo + so);
        size_t bo = (size_t)(nb*64 + r)*512 + kc*64 + q*8;
        CP_ASYNC16(dst + 2*MATB, g_Wfhi + bo);
        CP_ASYNC16(dst + 3*MATB, g_Wflo + bo);
    }
}
__global__ void __launch_bounds__(256)
k_pgmm(){
    extern __shared__ char sm[];
    int tid = threadIdx.x;
    int wid = tid >> 5, lane = tid & 31;
    int mb = blockIdx.x, nb = blockIdx.y;
    uint32_t sb = smem_u32(sm);

    int wm = wid & 1, wn = wid >> 1;
    float acc[2][2][4];
    #pragma unroll
    for (int mi = 0; mi < 2; mi++)
        #pragma unroll
        for (int ni = 0; ni < 2; ni++)
            #pragma unroll
            for (int q = 0; q < 4; q++) acc[mi][ni][q] = 0.f;

    uint32_t aRow = (uint32_t)(wm*32 + (lane & 15));
    uint32_t aCol = (uint32_t)((lane >> 4) * 8);
    uint32_t bRow = (uint32_t)(wn*16 + (lane & 7));
    uint32_t bCol = (uint32_t)(((lane >> 3) & 1) * 8);

    stage_proj(sb, 0, 0, mb, nb, tid);
    CP_COMMIT();
    for (int i = 0; i < 8; i++){
        int buf = i & 1;
        if (i + 1 < 8){
            stage_proj(sb, buf ^ 1, i + 1, mb, nb, tid);
            CP_COMMIT();
            CP_WAIT(1);
        } else CP_WAIT(0);
        __syncthreads();
        uint32_t base = sb + buf*BUFB4;
        #pragma unroll
        for (int ks = 0; ks < 4; ks++){
            uint32_t kb = (uint32_t)(ks*32);
            uint32_t ah[2][4], al[2][4], bh[2][2], bl[2][2];
            #pragma unroll
            for (int mi = 0; mi < 2; mi++){
                uint32_t ao = (aRow + mi*16)*144 + kb + aCol*2;
                ldm_x4(ah[mi], base + ao);
                ldm_x4(al[mi], base + MATB + ao);
            }
            #pragma unroll
            for (int ni = 0; ni < 2; ni++){
                uint32_t bo = (bRow + ni*8)*144 + kb + bCol*2;
                ldm_x2(bh[ni], base + 2*MATB + bo);
                ldm_x2(bl[ni], base + 3*MATB + bo);
            }
            #pragma unroll
            for (int mi = 0; mi < 2; mi++)
                #pragma unroll
                for (int ni = 0; ni < 2; ni++){
                    mma_bf16(acc[mi][ni], ah[mi], bh[ni]);
                    mma_bf16(acc[mi][ni], ah[mi], bl[ni]);
                    mma_bf16(acc[mi][ni], al[mi], bh[ni]);
                }
        }
        __syncthreads();
    }
    float* Cs = (float*)sm;
    #pragma unroll
    for (int mi = 0; mi < 2; mi++)
        #pragma unroll
        for (int ni = 0; ni < 2; ni++){
            int r0 = wm*32 + mi*16 + (lane >> 2);
            int c0 = wn*16 + ni*8 + (lane & 3)*2;
            Cs[r0*68 + c0]         = acc[mi][ni][0];
            Cs[r0*68 + c0 + 1]     = acc[mi][ni][1];
            Cs[(r0+8)*68 + c0]     = acc[mi][ni][2];
            Cs[(r0+8)*68 + c0 + 1] = acc[mi][ni][3];
        }
    __syncthreads();
    #pragma unroll
    for (int i = 0; i < 4; i++){
        int idx = tid + i*256;
        int r = idx >> 4, jl = idx & 15;
        *(float4*)&g_y[(size_t)(mb*64 + r)*128 + nb*64 + jl*4] =
            *(const float4*)&Cs[r*68 + jl*4];
    }
}

// ---------------- output transforms ----------------
__global__ void k_out(float* __restrict__ out, const float* __restrict__ bfc){
    int n = blockIdx.x*8 + (threadIdx.x >> 5);
    int lane = threadIdx.x & 31;
    int b = n / 257, t = n - b*257;
    const float* y = g_y + (size_t)(t*256 + b)*128;
    const int N = NROWS;
    float pi = (lane < 20) ? (y[3+lane] + bfc[3+lane]) : -3.4e38f;
    float m = pi;
    #pragma unroll
    for (int o = 16; o; o >>= 1) m = fmaxf(m, __shfl_xor_sync(0xffffffffu, m, o));
    float e = (lane < 20) ? __expf(pi - m) : 0.f;
    float s = e;
    #pragma unroll
    for (int o = 16; o; o >>= 1) s += __shfl_xor_sync(0xffffffffu, s, o);
    float inv = __fdividef(1.f, s);
    if (lane < 20){
        out[           n*20 + lane] = e*inv;
        out[  N*20   + n*20 + lane] = y[23 + lane] + bfc[23 + lane];
        out[2*N*20   + n*20 + lane] = y[43 + lane] + bfc[43 + lane];
        out[3*N*20   + n*20 + lane] = __expf(y[63 + lane] + bfc[63 + lane]);
        out[4*N*20   + n*20 + lane] = __expf(y[83 + lane] + bfc[83 + lane]);
        out[5*N*20   + n*20 + lane] = ftanh(y[103 + lane] + bfc[103 + lane]);
    }
    if (lane < 3)
        out[6*N*20 + n*3 + lane] = y[lane] + bfc[lane];
}

extern "C" void kernel_launch(void* const* d_in, const int* in_sizes, int n_in,
                              void* d_out, int out_size){
    const float* bbf    = (const float*)d_in[0];
    const float* z      = (const float*)d_in[1];
    const float* sk     = (const float*)d_in[2];
    const float* Wfc_hc = (const float*)d_in[3];
    const float* bfc_hc = (const float*)d_in[4];
    const float* Wch    = (const float*)d_in[5];
    const float* bch    = (const float*)d_in[6];
    const float* Kcf    = (const float*)d_in[7];
    const float* bcf    = (const float*)d_in[8];
    const float* Watt   = (const float*)d_in[9];
    const float* batt   = (const float*)d_in[10];
    const float* Wih    = (const float*)d_in[11];
    const float* Whh    = (const float*)d_in[12];
    const float* bih    = (const float*)d_in[13];
    const float* bhh    = (const float*)d_in[14];
    const float* Wfcp   = (const float*)d_in[15];
    const float* bfcp   = (const float*)d_in[16];
    float* out = (float*)d_out;

    cudaFuncSetAttribute(k_gmm,  cudaFuncAttributeMaxDynamicSharedMemorySize, SMEM_G2);
    cudaFuncSetAttribute(k_cgmm, cudaFuncAttributeMaxDynamicSharedMemorySize, SMEM_G4);
    cudaFuncSetAttribute(k_pgmm, cudaFuncAttributeMaxDynamicSharedMemorySize, SMEM_G4);

    k_wc   <<<4608, 256>>>(Kcf);
    k_im2  <<<256, 256>>>(bbf);
    k_bbh  <<<8192, 256>>>(bbf);
    k_wct2 <<<NCOL, 256>>>(Wih, Whh, bih, bhh, Wch);
    k_wfc  <<<128, 256>>>(Wfcp);
    k_init <<<256, 256>>>(z, Wfc_hc, bfc_hc);
    k_cgmm <<<dim3(256, 4), 256, SMEM_G4>>>(bcf);

    for (int t = 0; t < NSTEP; t++){
        k_gmm<<<dim3(4, 4), 256, SMEM_G2>>>(1, 8, t, bch);      // g_em
        k_attn2<<<128, 256>>>(t, Watt, batt, sk);               // attention
        k_gmm<<<dim3(4, 32), 256, SMEM_G2>>>(2, 17, t, nullptr);// full gates + LSTM
    }
    k_pgmm<<<dim3(1028, 2), 256, SMEM_G4>>>();
    k_out <<<8224, 256>>>(out, bfcp);
}

// round 15
// speedup vs baseline: 1.0537x; 1.0537x over previous
#include <cuda_runtime.h>
#include <cuda_bf16.h>
#include <cuda_fp16.h>
#include <cstdint>

#define BATCH   256
#define HDIM    512
#define EMBD    256
#define CFEAT   512
#define HWSZ    64
#define NSTEP   257
#define KDIM    1029
#define KP2     1088
#define NCOL    2304
#define NROWS   (BATCH*NSTEP)

// ---------------- device scratch ----------------
__device__ float g_c[BATCH*HDIM];
__device__ __half g_xem[BATCH*HWSZ*EMBD];
__device__ __half g_bbh[BATCH*CFEAT*HWSZ];
__device__ float g_y[NROWS*128];
__device__ float g_part[BATCH*2048];
__device__ float g_gem[BATCH*EMBD];
__device__ __half g_Ah[BATCH*KP2];
__device__ __half g_Bh[(size_t)NCOL*KP2];
__device__ float g_bsum[2048];
__device__ __nv_bfloat16 g_Phi[BATCH*100*512];
__device__ __nv_bfloat16 g_Plo[BATCH*100*512];
__device__ __nv_bfloat16 g_Chi[9*256*512];
__device__ __nv_bfloat16 g_Clo[9*256*512];
__device__ __half g_Hh[(size_t)NSTEP*BATCH*HDIM];   // fp16 h history
__device__ __half g_Wfh[128*512];                   // fp16 projection weights

// ---------------- math helpers ----------------
__device__ __forceinline__ float ftanh(float x){
    float x2 = x*x;
    float p = x*(135135.f + x2*(17325.f + x2*(378.f + x2)));
    float q = 135135.f + x2*(62370.f + x2*(3150.f + x2*28.f));
    float r = __int_as_float(0x7EF311C3u - __float_as_int(q));
    r = r*(2.f - q*r);
    r = r*(2.f - q*r);
    r = r*(2.f - q*r);
    float t = p*r;
    return fmaxf(-1.f, fminf(1.f, t));
}
__device__ __forceinline__ float fsig(float x){
    return 0.5f + 0.5f*ftanh(0.5f*x);
}
__device__ __forceinline__ float fatanh(float x){
    float y;
    asm("tanh.approx.f32 %0, %1;" : "=f"(y) : "f"(x));
    return y;
}

// ---------------- PTX helpers ----------------
__device__ __forceinline__ uint32_t smem_u32(const void* p){
    uint32_t a;
    asm("{ .reg .u64 t; cvta.to.shared.u64 t, %1; cvt.u32.u64 %0, t; }" : "=r"(a) : "l"(p));
    return a;
}
#define CP_ASYNC16(dst, src) \
    asm volatile("cp.async.cg.shared.global [%0], [%1], 16;" :: "r"(dst), "l"(src))
#define CP_COMMIT()  asm volatile("cp.async.commit_group;" ::: "memory")
#define CP_WAIT(n)   asm volatile("cp.async.wait_group %0;" :: "n"(n) : "memory")

__device__ __forceinline__ void ldm_x4(uint32_t* r, uint32_t addr){
    asm volatile("ldmatrix.sync.aligned.m8n8.x4.shared.b16 {%0,%1,%2,%3}, [%4];"
        : "=r"(r[0]), "=r"(r[1]), "=r"(r[2]), "=r"(r[3]) : "r"(addr));
}
__device__ __forceinline__ void ldm_x2(uint32_t* r, uint32_t addr){
    asm volatile("ldmatrix.sync.aligned.m8n8.x2.shared.b16 {%0,%1}, [%2];"
        : "=r"(r[0]), "=r"(r[1]) : "r"(addr));
}
__device__ __forceinline__ void mma_bf16(float* c, const uint32_t* a, const uint32_t* b){
    asm volatile("mma.sync.aligned.m16n8k16.row.col.f32.bf16.bf16.f32 "
        "{%0,%1,%2,%3}, {%4,%5,%6,%7}, {%8,%9}, {%0,%1,%2,%3};"
        : "+f"(c[0]), "+f"(c[1]), "+f"(c[2]), "+f"(c[3])
        : "r"(a[0]), "r"(a[1]), "r"(a[2]), "r"(a[3]), "r"(b[0]), "r"(b[1]));
}
__device__ __forceinline__ void mma_f16(float* c, const uint32_t* a, const uint32_t* b){
    asm volatile("mma.sync.aligned.m16n8k16.row.col.f32.f16.f16.f32 "
        "{%0,%1,%2,%3}, {%4,%5,%6,%7}, {%8,%9}, {%0,%1,%2,%3};"
        : "+f"(c[0]), "+f"(c[1]), "+f"(c[2]), "+f"(c[3])
        : "r"(a[0]), "r"(a[1]), "r"(a[2]), "r"(a[3]), "r"(b[0]), "r"(b[1]));
}

// smem geometry
#define MATB     9216
#define BUFB4    36864
#define OFF_BS4  73728
#define SMEM_G4  (OFF_BS4 + 256)
#define BUFB2    18432
#define OFF_BS2  36864
#define SMEM_G2  (OFF_BS2 + 256)

// ---------------- weight prep ----------------
__global__ void k_wct2(const float* __restrict__ Wih, const float* __restrict__ Whh,
                       const float* __restrict__ bih, const float* __restrict__ bhh,
                       const float* __restrict__ Wch){
    int col = blockIdx.x;
    if (col < 2048){
        int j = col >> 2, g = col & 3;
        int row = g*512 + j;
        for (int k = threadIdx.x; k < KP2; k += 256){
            float v = 0.f;
            if (k < 512)        v = Whh[row*512 + k];
            else if (k < 1024)  v = Wih[row*517 + (k - 512)];
            else if (k < 1029)  v = Wih[row*517 + 512 + (k - 1024)];
            g_Bh[(size_t)col*KP2 + k] = __float2half_rn(v);
        }
        if (threadIdx.x == 0) g_bsum[col] = bih[row] + bhh[row];
    } else {
        int e = col - 2048;
        for (int k = threadIdx.x; k < KP2; k += 256){
            float v = (k < 512) ? Wch[e*512 + k] : 0.f;
            g_Bh[(size_t)col*KP2 + k] = __float2half_rn(v);
        }
    }
}
__global__ void k_wc(const float* __restrict__ Kcf){
    int idx = blockIdx.x*256 + threadIdx.x;
    int c = idx & 511, r = idx >> 9;
    int e = r & 255, tap = r >> 8;
    float v = Kcf[e*4608 + c*9 + tap];
    __nv_bfloat16 hi = __float2bfloat16_rn(v);
    g_Chi[idx] = hi;
    g_Clo[idx] = __float2bfloat16_rn(v - __bfloat162float(hi));
}
__global__ void k_im2(const float* __restrict__ bbf){
    int b = blockIdx.x;
    for (int idx = threadIdx.x; idx < 100*512; idx += 256){
        int pos = idx >> 9, c = idx & 511;
        int py = pos/10 - 1, px = pos%10 - 1;
        float v = 0.f;
        if (py >= 0 && py < 8 && px >= 0 && px < 8)
            v = bbf[(b*512 + c)*64 + py*8 + px];
        __nv_bfloat16 hi = __float2bfloat16_rn(v);
        g_Phi[b*51200 + idx] = hi;
        g_Plo[b*51200 + idx] = __float2bfloat16_rn(v - __bfloat162float(hi));
    }
}
__global__ void k_bbh(const float* __restrict__ bbf){
    int idx = blockIdx.x*256 + threadIdx.x;
    const float4 v = ((const float4*)bbf)[idx];
    __half2 h0 = __floats2half2_rn(v.x, v.y);
    __half2 h1 = __floats2half2_rn(v.z, v.w);
    ((uint2*)g_bbh)[idx] = make_uint2(*(uint32_t*)&h0, *(uint32_t*)&h1);
}
__global__ void k_wfc(const float* __restrict__ Wfc){
    int col = blockIdx.x;
    for (int k = threadIdx.x; k < 512; k += 256){
        float v = (col < 123) ? Wfc[col*512 + k] : 0.f;
        g_Wfh[col*512 + k] = __float2half_rn(v);
    }
}

// ---------------- init hc ----------------
__global__ void k_init(const float* __restrict__ z, const float* __restrict__ W,
                       const float* __restrict__ bias){
    int b = blockIdx.x, tid = threadIdx.x;
    __shared__ float zs[128];
    if (tid < 128) zs[tid] = z[b*128 + tid];
    if (tid < 59) g_Ah[b*KP2 + KDIM + tid] = __float2half_rn(0.f);
    __syncthreads();
    for (int j = tid; j < 1024; j += 256){
        const float4* wr = (const float4*)(W + j*128);
        const float4* zr = (const float4*)zs;
        float acc = bias[j];
        #pragma unroll 8
        for (int k = 0; k < 32; k++){
            float4 w = wr[k], zz = zr[k];
            acc += w.x*zz.x + w.y*zz.y + w.z*zz.z + w.w*zz.w;
        }
        float v = ftanh(acc);
        if (j < 512) g_Ah[b*KP2 + j] = __float2half_rn(v);
        else         g_c[b*512 + (j - 512)] = v;
    }
}

// ---------------- conv as 9-tap HMMA GEMM (bf16 3-term) ----------------
__device__ __forceinline__ void stage_conv(uint32_t sb, int buf, int cc,
                                           int mb, int nb, int tid){
    int tap = cc >> 3, kc = cc & 7;
    int toff = (tap/3)*10 + (tap%3);
    uint32_t dbase = sb + buf*BUFB4;
    #pragma unroll
    for (int i = 0; i < 2; i++){
        int idx = tid + i*256;
        int r = idx >> 3, q = idx & 7;
        int arow = mb*100 + (r >> 3)*10 + (r & 7) + toff;
        size_t so = (size_t)arow*512 + kc*64 + q*8;
        uint32_t dst = dbase + r*144 + q*16;
        CP_ASYNC16(dst,        g_Phi + so);
        CP_ASYNC16(dst + MATB, g_Plo + so);
        int brow = tap*256 + nb*64 + r;
        size_t bo = (size_t)brow*512 + kc*64 + q*8;
        CP_ASYNC16(dst + 2*MATB, g_Chi + bo);
        CP_ASYNC16(dst + 3*MATB, g_Clo + bo);
    }
}
__global__ void __launch_bounds__(256)
k_cgmm(const float* __restrict__ bcf){
    extern __shared__ char sm[];
    int tid = threadIdx.x;
    int wid = tid >> 5, lane = tid & 31;
    int mb = blockIdx.x, nb = blockIdx.y;
    uint32_t sb = smem_u32(sm);
    float* bs = (float*)(sm + OFF_BS4);
    if (tid < 64) bs[tid] = bcf[nb*64 + tid];

    int wm = wid & 1, wn = wid >> 1;
    float acc[2][2][4];
    #pragma unroll
    for (int mi = 0; mi < 2; mi++)
        #pragma unroll
        for (int ni = 0; ni < 2; ni++)
            #pragma unroll
            for (int q = 0; q < 4; q++) acc[mi][ni][q] = 0.f;

    uint32_t aRow = (uint32_t)(wm*32 + (lane & 15));
    uint32_t aCol = (uint32_t)((lane >> 4) * 8);
    uint32_t bRow = (uint32_t)(wn*16 + (lane & 7));
    uint32_t bCol = (uint32_t)(((lane >> 3) & 1) * 8);

    stage_conv(sb, 0, 0, mb, nb, tid);
    CP_COMMIT();
    for (int cc = 0; cc < 72; cc++){
        int buf = cc & 1;
        if (cc + 1 < 72){
            stage_conv(sb, buf ^ 1, cc + 1, mb, nb, tid);
            CP_COMMIT();
            CP_WAIT(1);
        } else CP_WAIT(0);
        __syncthreads();
        uint32_t base = sb + buf*BUFB4;
        #pragma unroll
        for (int ks = 0; ks < 4; ks++){
            uint32_t kb = (uint32_t)(ks*32);
            uint32_t ah[2][4], al[2][4], bh[2][2], bl[2][2];
            #pragma unroll
            for (int mi = 0; mi < 2; mi++){
                uint32_t ao = (aRow + mi*16)*144 + kb + aCol*2;
                ldm_x4(ah[mi], base + ao);
                ldm_x4(al[mi], base + MATB + ao);
            }
            #pragma unroll
            for (int ni = 0; ni < 2; ni++){
                uint32_t bo = (bRow + ni*8)*144 + kb + bCol*2;
                ldm_x2(bh[ni], base + 2*MATB + bo);
                ldm_x2(bl[ni], base + 3*MATB + bo);
            }
            #pragma unroll
            for (int mi = 0; mi < 2; mi++)
                #pragma unroll
                for (int ni = 0; ni < 2; ni++){
                    mma_bf16(acc[mi][ni], ah[mi], bh[ni]);
                    mma_bf16(acc[mi][ni], ah[mi], bl[ni]);
                    mma_bf16(acc[mi][ni], al[mi], bh[ni]);
                }
        }
        __syncthreads();
    }
    float* Cs = (float*)sm;
    #pragma unroll
    for (int mi = 0; mi < 2; mi++)
        #pragma unroll
        for (int ni = 0; ni < 2; ni++){
            int r0 = wm*32 + mi*16 + (lane >> 2);
            int c0 = wn*16 + ni*8 + (lane & 3)*2;
            Cs[r0*68 + c0]         = acc[mi][ni][0];
            Cs[r0*68 + c0 + 1]     = acc[mi][ni][1];
            Cs[(r0+8)*68 + c0]     = acc[mi][ni][2];
            Cs[(r0+8)*68 + c0 + 1] = acc[mi][ni][3];
        }
    __syncthreads();
    #pragma unroll
    for (int i = 0; i < 4; i++){
        int idx = tid + i*256;
        int r = idx >> 4, jl = idx & 15;
        float4 g4 = *(const float4*)&Cs[r*68 + jl*4];
        float4 b4 = *(const float4*)&bs[jl*4];
        __half2 h0 = __floats2half2_rn(g4.x+b4.x, g4.y+b4.y);
        __half2 h1 = __floats2half2_rn(g4.z+b4.z, g4.w+b4.w);
        uint2 pk = make_uint2(*(uint32_t*)&h0, *(uint32_t*)&h1);
        *(uint2*)&g_xem[(mb*64 + r)*256 + nb*64 + jl*4] = pk;
    }
}

// ---------------- attention (MUFU scores) ----------------
__global__ void k_attn2(int t,
                        const float* __restrict__ Watt, const float* __restrict__ batt,
                        const float* __restrict__ sketch){
    int b0 = blockIdx.x * 2, tid = threadIdx.x;
    __shared__ float g_s[2][256];
    __shared__ float sc[2][64];

    #pragma unroll
    for (int i = 0; i < 2; i++){
        int idx = tid + i*256;
        int bb = idx >> 8, e = idx & 255;
        g_s[bb][e] = g_gem[(b0+bb)*EMBD + e];
    }
    __syncthreads();
    {
        int pair = tid >> 1, half = tid & 1;
        int bb = pair >> 6, p = pair & 63;
        const uint2* xr = (const uint2*)(g_xem + ((b0+bb)*HWSZ + p)*EMBD + half*128);
        const float4* wa = (const float4*)(Watt + half*128);
        const float4* gv4 = (const float4*)(g_s[bb] + half*128);
        float acc = 0.f;
        #pragma unroll 4
        for (int k = 0; k < 32; k++){
            uint2 xu = xr[k];
            float2 x0 = __half22float2(*(__half2*)&xu.x);
            float2 x1 = __half22float2(*(__half2*)&xu.y);
            float4 w = wa[k], gv = gv4[k];
            acc += fatanh(x0.x+gv.x)*w.x + fatanh(x0.y+gv.y)*w.y
                 + fatanh(x1.x+gv.z)*w.z + fatanh(x1.y+gv.w)*w.w;
        }
        acc += __shfl_xor_sync(0xffffffffu, acc, 1);
        if (half == 0) sc[bb][p] = acc + batt[0];
    }
    __syncthreads();
    if (tid < 64){
        int bb = tid >> 5, lane = tid & 31;
        float v0 = sc[bb][lane], v1 = sc[bb][lane+32];
        float m = fmaxf(v0, v1);
        #pragma unroll
        for (int o = 16; o; o >>= 1) m = fmaxf(m, __shfl_xor_sync(0xffffffffu, m, o));
        float e0 = __expf(v0 - m), e1 = __expf(v1 - m);
        float s = e0 + e1;
        #pragma unroll
        for (int o = 16; o; o >>= 1) s += __shfl_xor_sync(0xffffffffu, s, o);
        float inv = __fdividef(1.f, s);
        sc[bb][lane] = e0*inv; sc[bb][lane+32] = e1*inv;
    }
    __syncthreads();
    #pragma unroll
    for (int bb = 0; bb < 2; bb++){
        #pragma unroll
        for (int cc = 0; cc < 2; cc++){
            int ch = tid + cc*256;
            const uint2* fr = (const uint2*)(g_bbh + ((b0+bb)*CFEAT + ch)*HWSZ);
            float acc = 0.f;
            #pragma unroll
            for (int k = 0; k < 16; k++){
                uint2 fu = fr[k];
                float2 f0 = __half22float2(*(__half2*)&fu.x);
                float2 f1 = __half22float2(*(__half2*)&fu.y);
                acc += sc[bb][k*4+0]*f0.x + sc[bb][k*4+1]*f0.y
                     + sc[bb][k*4+2]*f1.x + sc[bb][k*4+3]*f1.y;
            }
            g_Ah[(b0+bb)*KP2 + 512 + ch] = __float2half_rn(acc);
        }
    }
    if (tid < 10){
        int bb = tid / 5, d = tid % 5;
        float v = (t == 0) ? ((d == 2) ? 1.f : 0.f)
                           : sketch[((t-1)*BATCH + (b0+bb))*5 + d];
        g_Ah[(b0+bb)*KP2 + 1024 + d] = __float2half_rn(v);
    }
}

// ---------------- gates GEMM staging (2 matrices: A, B) --------------
__device__ __forceinline__ void stage_chunk(uint32_t sb, int buf, int kc,
                                            int mb, int nb, int tid){
    uint32_t dbase = sb + buf*BUFB2;
    #pragma unroll
    for (int i = 0; i < 2; i++){
        int idx = tid + i*256;
        int r = idx >> 3, q = idx & 7;
        size_t so = (size_t)(mb*64 + r)*KP2 + kc*64 + q*8;
        uint32_t dst = dbase + r*144 + q*16;
        CP_ASYNC16(dst, g_Ah + so);
        size_t bo = (size_t)(nb*64 + r)*KP2 + kc*64 + q*8;
        CP_ASYNC16(dst + MATB, g_Bh + bo);
    }
}

// ---------------- gates 1-term fp16 HMMA GEMM ----------------
// mode 0 (h-phase): K 0..511, nb 0..35 -> nb<32: g_part, nb>=32: g_gem+bch
// mode 2 (x-phase): K 512..1087, nb 0..31 -> + g_part + bsum -> LSTM epilogue
__global__ void __launch_bounds__(256)
k_gmm(int mode, int kclo, int nkc, int t, const float* __restrict__ bch){
    extern __shared__ char sm[];
    int tid = threadIdx.x;
    int wid = tid >> 5, lane = tid & 31;
    int mb = blockIdx.x;
    int nb = blockIdx.y;
    uint32_t sb = smem_u32(sm);

    float* bs = (float*)(sm + OFF_BS2);
    if (mode == 2){ if (tid < 64) bs[tid] = g_bsum[nb*64 + tid]; }
    else if (nb >= 32){ if (tid < 64) bs[tid] = bch[(nb-32)*64 + tid]; }

    int wm = wid & 1, wn = wid >> 1;
    float acc[2][2][4];
    #pragma unroll
    for (int mi = 0; mi < 2; mi++)
        #pragma unroll
        for (int ni = 0; ni < 2; ni++)
            #pragma unroll
            for (int q = 0; q < 4; q++) acc[mi][ni][q] = 0.f;

    uint32_t aRow = (uint32_t)(wm*32 + (lane & 15));
    uint32_t aCol = (uint32_t)((lane >> 4) * 8);
    uint32_t bRow = (uint32_t)(wn*16 + (lane & 7));
    uint32_t bCol = (uint32_t)(((lane >> 3) & 1) * 8);

    stage_chunk(sb, 0, kclo, mb, nb, tid);
    CP_COMMIT();
    for (int i = 0; i < nkc; i++){
        int buf = i & 1;
        if (i + 1 < nkc){
            stage_chunk(sb, buf ^ 1, kclo + i + 1, mb, nb, tid);
            CP_COMMIT();
            CP_WAIT(1);
        } else CP_WAIT(0);
        __syncthreads();
        uint32_t base = sb + buf*BUFB2;
        #pragma unroll
        for (int ks = 0; ks < 4; ks++){
            uint32_t kb = (uint32_t)(ks*32);
            uint32_t ah[2][4], bh[2][2];
            #pragma unroll
            for (int mi = 0; mi < 2; mi++){
                uint32_t ao = (aRow + mi*16)*144 + kb + aCol*2;
                ldm_x4(ah[mi], base + ao);
            }
            #pragma unroll
            for (int ni = 0; ni < 2; ni++){
                uint32_t bo = (bRow + ni*8)*144 + kb + bCol*2;
                ldm_x2(bh[ni], base + MATB + bo);
            }
            #pragma unroll
            for (int mi = 0; mi < 2; mi++)
                #pragma unroll
                for (int ni = 0; ni < 2; ni++)
                    mma_f16(acc[mi][ni], ah[mi], bh[ni]);
        }
        __syncthreads();
    }

    float* Cs = (float*)sm;
    #pragma unroll
    for (int mi = 0; mi < 2; mi++)
        #pragma unroll
        for (int ni = 0; ni < 2; ni++){
            int r0 = wm*32 + mi*16 + (lane >> 2);
            int c0 = wn*16 + ni*8 + (lane & 3)*2;
            Cs[r0*68 + c0]         = acc[mi][ni][0];
            Cs[r0*68 + c0 + 1]     = acc[mi][ni][1];
            Cs[(r0+8)*68 + c0]     = acc[mi][ni][2];
            Cs[(r0+8)*68 + c0 + 1] = acc[mi][ni][3];
        }
    __syncthreads();

    if (mode == 0){
        if (nb < 32){
            #pragma unroll
            for (int i = 0; i < 4; i++){
                int idx = tid + i*256;
                int bl_ = idx >> 4, jl = idx & 15;
                int b = mb*64 + bl_;
                *(float4*)&g_part[b*2048 + nb*64 + jl*4] = *(const float4*)&Cs[bl_*68 + jl*4];
            }
        } else {
            #pragma unroll
            for (int i = 0; i < 4; i++){
                int idx = tid + i*256;
                int bl_ = idx >> 4, jl = idx & 15;
                int b = mb*64 + bl_;
                float4 g4 = *(const float4*)&Cs[bl_*68 + jl*4];
                float4 b4 = *(const float4*)&bs[jl*4];
                *(float4*)&g_gem[b*EMBD + (nb-32)*64 + jl*4] =
                    make_float4(g4.x+b4.x, g4.y+b4.y, g4.z+b4.z, g4.w+b4.w);
            }
        }
    } else {
        #pragma unroll
        for (int i = 0; i < 4; i++){
            int idx = tid + i*256;
            int bl_ = idx >> 4, jl = idx & 15;
            int b = mb*64 + bl_;
            int j = nb*16 + jl;
            float4 g4 = *(const float4*)&Cs[bl_*68 + jl*4];
            float4 p4 = *(const float4*)&g_part[b*2048 + nb*64 + jl*4];
            float4 b4 = *(const float4*)&bs[jl*4];
            float iv = fsig (g4.x + p4.x + b4.x);
            float fv = fsig (g4.y + p4.y + b4.y);
            float gv = ftanh(g4.z + p4.z + b4.z);
            float ov = fsig (g4.w + p4.w + b4.w);
            float cold = g_c[b*512 + j];
            float cnew = fv*cold + iv*gv;
            float hnew = ov*ftanh(cnew);
            g_c[b*512 + j] = cnew;
            __half hh = __float2half_rn(hnew);
            g_Ah[b*KP2 + j] = hh;
            g_Hh[(size_t)(t*BATCH + b)*512 + j] = hh;
        }
    }
}

// ---------------- projection GEMM (1-term fp16) ----------------
__device__ __forceinline__ void stage_proj(uint32_t sb, int buf, int kc,
                                           int mb, int nb, int tid){
    uint32_t dbase = sb + buf*BUFB2;
    #pragma unroll
    for (int i = 0; i < 2; i++){
        int idx = tid + i*256;
        int r = idx >> 3, q = idx & 7;
        size_t so = (size_t)(mb*64 + r)*512 + kc*64 + q*8;
        uint32_t dst = dbase + r*144 + q*16;
        CP_ASYNC16(dst, g_Hh + so);
        size_t bo = (size_t)(nb*64 + r)*512 + kc*64 + q*8;
        CP_ASYNC16(dst + MATB, g_Wfh + bo);
    }
}
__global__ void __launch_bounds__(256)
k_pgmm(){
    extern __shared__ char sm[];
    int tid = threadIdx.x;
    int wid = tid >> 5, lane = tid & 31;
    int mb = blockIdx.x, nb = blockIdx.y;
    uint32_t sb = smem_u32(sm);

    int wm = wid & 1, wn = wid >> 1;
    float acc[2][2][4];
    #pragma unroll
    for (int mi = 0; mi < 2; mi++)
        #pragma unroll
        for (int ni = 0; ni < 2; ni++)
            #pragma unroll
            for (int q = 0; q < 4; q++) acc[mi][ni][q] = 0.f;

    uint32_t aRow = (uint32_t)(wm*32 + (lane & 15));
    uint32_t aCol = (uint32_t)((lane >> 4) * 8);
    uint32_t bRow = (uint32_t)(wn*16 + (lane & 7));
    uint32_t bCol = (uint32_t)(((lane >> 3) & 1) * 8);

    stage_proj(sb, 0, 0, mb, nb, tid);
    CP_COMMIT();
    for (int i = 0; i < 8; i++){
        int buf = i & 1;
        if (i + 1 < 8){
            stage_proj(sb, buf ^ 1, i + 1, mb, nb, tid);
            CP_COMMIT();
            CP_WAIT(1);
        } else CP_WAIT(0);
        __syncthreads();
        uint32_t base = sb + buf*BUFB2;
        #pragma unroll
        for (int ks = 0; ks < 4; ks++){
            uint32_t kb = (uint32_t)(ks*32);
            uint32_t ah[2][4], bh[2][2];
            #pragma unroll
            for (int mi = 0; mi < 2; mi++){
                uint32_t ao = (aRow + mi*16)*144 + kb + aCol*2;
                ldm_x4(ah[mi], base + ao);
            }
            #pragma unroll
            for (int ni = 0; ni < 2; ni++){
                uint32_t bo = (bRow + ni*8)*144 + kb + bCol*2;
                ldm_x2(bh[ni], base + MATB + bo);
            }
            #pragma unroll
            for (int mi = 0; mi < 2; mi++)
                #pragma unroll
                for (int ni = 0; ni < 2; ni++)
                    mma_f16(acc[mi][ni], ah[mi], bh[ni]);
        }
        __syncthreads();
    }
    float* Cs = (float*)sm;
    #pragma unroll
    for (int mi = 0; mi < 2; mi++)
        #pragma unroll
        for (int ni = 0; ni < 2; ni++){
            int r0 = wm*32 + mi*16 + (lane >> 2);
            int c0 = wn*16 + ni*8 + (lane & 3)*2;
            Cs[r0*68 + c0]         = acc[mi][ni][0];
            Cs[r0*68 + c0 + 1]     = acc[mi][ni][1];
            Cs[(r0+8)*68 + c0]     = acc[mi][ni][2];
            Cs[(r0+8)*68 + c0 + 1] = acc[mi][ni][3];
        }
    __syncthreads();
    #pragma unroll
    for (int i = 0; i < 4; i++){
        int idx = tid + i*256;
        int r = idx >> 4, jl = idx & 15;
        *(float4*)&g_y[(size_t)(mb*64 + r)*128 + nb*64 + jl*4] =
            *(const float4*)&Cs[r*68 + jl*4];
    }
}

// ---------------- output transforms ----------------
__global__ void k_out(float* __restrict__ out, const float* __restrict__ bfc){
    int n = blockIdx.x*8 + (threadIdx.x >> 5);
    int lane = threadIdx.x & 31;
    int b = n / 257, t = n - b*257;
    const float* y = g_y + (size_t)(t*256 + b)*128;
    const int N = NROWS;
    float pi = (lane < 20) ? (y[3+lane] + bfc[3+lane]) : -3.4e38f;
    float m = pi;
    #pragma unroll
    for (int o = 16; o; o >>= 1) m = fmaxf(m, __shfl_xor_sync(0xffffffffu, m, o));
    float e = (lane < 20) ? __expf(pi - m) : 0.f;
    float s = e;
    #pragma unroll
    for (int o = 16; o; o >>= 1) s += __shfl_xor_sync(0xffffffffu, s, o);
    float inv = __fdividef(1.f, s);
    if (lane < 20){
        out[           n*20 + lane] = e*inv;
        out[  N*20   + n*20 + lane] = y[23 + lane] + bfc[23 + lane];
        out[2*N*20   + n*20 + lane] = y[43 + lane] + bfc[43 + lane];
        out[3*N*20   + n*20 + lane] = __expf(y[63 + lane] + bfc[63 + lane]);
        out[4*N*20   + n*20 + lane] = __expf(y[83 + lane] + bfc[83 + lane]);
        out[5*N*20   + n*20 + lane] = ftanh(y[103 + lane] + bfc[103 + lane]);
    }
    if (lane < 3)
        out[6*N*20 + n*3 + lane] = y[lane] + bfc[lane];
}

extern "C" void kernel_launch(void* const* d_in, const int* in_sizes, int n_in,
                              void* d_out, int out_size){
    const float* bbf    = (const float*)d_in[0];
    const float* z      = (const float*)d_in[1];
    const float* sk     = (const float*)d_in[2];
    const float* Wfc_hc = (const float*)d_in[3];
    const float* bfc_hc = (const float*)d_in[4];
    const float* Wch    = (const float*)d_in[5];
    const float* bch    = (const float*)d_in[6];
    const float* Kcf    = (const float*)d_in[7];
    const float* bcf    = (const float*)d_in[8];
    const float* Watt   = (const float*)d_in[9];
    const float* batt   = (const float*)d_in[10];
    const float* Wih    = (const float*)d_in[11];
    const float* Whh    = (const float*)d_in[12];
    const float* bih    = (const float*)d_in[13];
    const float* bhh    = (const float*)d_in[14];
    const float* Wfcp   = (const float*)d_in[15];
    const float* bfcp   = (const float*)d_in[16];
    float* out = (float*)d_out;

    cudaFuncSetAttribute(k_gmm,  cudaFuncAttributeMaxDynamicSharedMemorySize, SMEM_G2);
    cudaFuncSetAttribute(k_cgmm, cudaFuncAttributeMaxDynamicSharedMemorySize, SMEM_G4);
    cudaFuncSetAttribute(k_pgmm, cudaFuncAttributeMaxDynamicSharedMemorySize, SMEM_G2);

    k_wc   <<<4608, 256>>>(Kcf);
    k_im2  <<<256, 256>>>(bbf);
    k_bbh  <<<8192, 256>>>(bbf);
    k_wct2 <<<NCOL, 256>>>(Wih, Whh, bih, bhh, Wch);
    k_wfc  <<<128, 256>>>(Wfcp);
    k_init <<<256, 256>>>(z, Wfc_hc, bfc_hc);
    k_cgmm <<<dim3(256, 4), 256, SMEM_G4>>>(bcf);

    for (int t = 0; t < NSTEP; t++){
        k_gmm<<<dim3(4, 36), 256, SMEM_G2>>>(0, 0, 8, t, bch);
        k_attn2<<<128, 256>>>(t, Watt, batt, sk);
        k_gmm<<<dim3(4, 32), 256, SMEM_G2>>>(2, 8, 9, t, nullptr);
    }
    k_pgmm<<<dim3(1028, 2), 256, SMEM_G2>>>();
    k_out <<<8224, 256>>>(out, bfcp);
}